// round 14
// baseline (speedup 1.0000x reference)
#include <cuda_runtime.h>

// Group ZCA whitening: x (64, 256, 56, 56) fp32, 64 groups of 4 channels.
// R14: R13 base + Programmatic Dependent Launch. Stats blocks signal
// launch_dependents right after publishing partials (before the last-arrival
// inline solve), so the apply grid launches while the final solves run.
// Apply blocks prefetch their own 50KB x-tile into L2 (x is independent of
// stats), then griddepcontrol.wait (full primary completion + mem visibility)
// before reading W/bias. Hides the solve tail + launch gap + apply cold-start.

#define NB   64      // batches
#define NG   64      // groups
#define NCH  256     // channels
#define SP   3136    // 56*56
#define SP4  784     // SP / 4
#define EPSF 1e-3f

__device__ float g_part[NG * NB * 14];   // [group][batch][4 sums + 10 moments]
__device__ float g_W[NG * 16];
__device__ float g_bias[NG * 4];
__device__ unsigned int g_cnt[NG];       // per-group arrival counters (self-resetting)

// ---------------------------------------------------------------------------
// fp32 4x4 symmetric Jacobi solve for group g (validated: rel_err ~4.8e-7).
// ---------------------------------------------------------------------------
__device__ void solve_group(int g) {
    const int t = threadIdx.x;

    float vals[14];
    if (t < NB) {
        #pragma unroll
        for (int k = 0; k < 14; k++)
            vals[k] = g_part[((size_t)g * NB + t) * 14 + k];
    } else {
        #pragma unroll
        for (int k = 0; k < 14; k++) vals[k] = 0.f;
    }

    const int lane = t & 31;
    const int warp = t >> 5;
    #pragma unroll
    for (int k = 0; k < 14; k++) {
        #pragma unroll
        for (int o = 16; o > 0; o >>= 1)
            vals[k] += __shfl_down_sync(0xffffffffu, vals[k], o);
    }
    __shared__ float sv[2][14];
    if (lane == 0 && warp < 2) {
        #pragma unroll
        for (int k = 0; k < 14; k++) sv[warp][k] = vals[k];
    }
    __syncthreads();

    if (t == 0) {
        float S[4], Q[10];
        #pragma unroll
        for (int k = 0; k < 4; k++) S[k] = sv[0][k] + sv[1][k];
        #pragma unroll
        for (int k = 0; k < 10; k++) Q[k] = sv[0][4 + k] + sv[1][4 + k];

        const float n = (float)NB * (float)SP;
        float m[4];
        #pragma unroll
        for (int k = 0; k < 4; k++) m[k] = S[k] / n;

        float A[4][4];
        const int qi[4][4] = {{0,1,2,3},{1,4,5,6},{2,5,7,8},{3,6,8,9}};
        for (int i = 0; i < 4; i++)
            for (int j = 0; j < 4; j++) {
                float c = Q[qi[i][j]] - n * m[i] * m[j];
                A[i][j] = (1.0f - EPSF) * c + (i == j ? EPSF : 0.0f);
            }

        float V[4][4] = {{1,0,0,0},{0,1,0,0},{0,0,1,0},{0,0,0,1}};
        for (int sweep = 0; sweep < 12; sweep++) {
            float off = fabsf(A[0][1]) + fabsf(A[0][2]) + fabsf(A[0][3])
                      + fabsf(A[1][2]) + fabsf(A[1][3]) + fabsf(A[2][3]);
            if (off < 1e-6f * (fabsf(A[0][0]) + fabsf(A[1][1]) + fabsf(A[2][2]) + fabsf(A[3][3]) + 1e-30f))
                break;
            for (int p = 0; p < 3; p++)
                for (int q = p + 1; q < 4; q++) {
                    float apq = A[p][q];
                    if (fabsf(apq) < 1e-30f) continue;
                    float theta = (A[q][q] - A[p][p]) / (2.0f * apq);
                    float tt = (theta >= 0.0f ? 1.0f : -1.0f) / (fabsf(theta) + sqrtf(theta * theta + 1.0f));
                    float c = 1.0f / sqrtf(tt * tt + 1.0f);
                    float s = tt * c;
                    for (int k = 0; k < 4; k++) {
                        float akp = A[k][p], akq = A[k][q];
                        A[k][p] = c * akp - s * akq;
                        A[k][q] = s * akp + c * akq;
                    }
                    for (int k = 0; k < 4; k++) {
                        float apk = A[p][k], aqk = A[q][k];
                        A[p][k] = c * apk - s * aqk;
                        A[q][k] = s * apk + c * aqk;
                    }
                    for (int k = 0; k < 4; k++) {
                        float vkp = V[k][p], vkq = V[k][q];
                        V[k][p] = c * vkp - s * vkq;
                        V[k][q] = s * vkp + c * vkq;
                    }
                }
        }

        float inv[4];
        #pragma unroll
        for (int k = 0; k < 4; k++) inv[k] = 1.0f / sqrtf(A[k][k] + EPSF);

        for (int i = 0; i < 4; i++) {
            float bsum = 0.0f;
            #pragma unroll
            for (int j = 0; j < 4; j++) {
                float w = 0.0f;
                #pragma unroll
                for (int k = 0; k < 4; k++) w += V[i][k] * inv[k] * V[j][k];
                g_W[g * 16 + i * 4 + j] = w;
                bsum += w * m[j];
            }
            g_bias[g * 4 + i] = bsum;
        }
    }
}

// ---------------------------------------------------------------------------
// Pass 1: stats + inline last-block solve. grid (NB, NG), b fastest.
// Signals launch_dependents BEFORE the solve so apply can launch early.
// ---------------------------------------------------------------------------
__global__ __launch_bounds__(256, 6) void stats_kernel(const float* __restrict__ x) {
    const int b = blockIdx.x;
    const int g = blockIdx.y;
    const int tid = threadIdx.x;
    const size_t base = ((size_t)b * NCH + (size_t)g * 4) * SP;
    const float4* __restrict__ c0 = (const float4*)(x + base);
    const float4* __restrict__ c1 = c0 + SP4;
    const float4* __restrict__ c2 = c0 + 2 * SP4;
    const float4* __restrict__ c3 = c0 + 3 * SP4;

    float s0 = 0.f, s1 = 0.f, s2 = 0.f, s3 = 0.f;
    float q00 = 0.f, q01 = 0.f, q02 = 0.f, q03 = 0.f;
    float q11 = 0.f, q12 = 0.f, q13 = 0.f;
    float q22 = 0.f, q23 = 0.f, q33 = 0.f;

    for (int i = tid; i < SP4; i += 256) {
        float4 a = c0[i];
        float4 e = c1[i];
        float4 f = c2[i];
        float4 h = c3[i];
        s0 += a.x + a.y + a.z + a.w;
        s1 += e.x + e.y + e.z + e.w;
        s2 += f.x + f.y + f.z + f.w;
        s3 += h.x + h.y + h.z + h.w;
        q00 += a.x*a.x + a.y*a.y + a.z*a.z + a.w*a.w;
        q01 += a.x*e.x + a.y*e.y + a.z*e.z + a.w*e.w;
        q02 += a.x*f.x + a.y*f.y + a.z*f.z + a.w*f.w;
        q03 += a.x*h.x + a.y*h.y + a.z*h.z + a.w*h.w;
        q11 += e.x*e.x + e.y*e.y + e.z*e.z + e.w*e.w;
        q12 += e.x*f.x + e.y*f.y + e.z*f.z + e.w*f.w;
        q13 += e.x*h.x + e.y*h.y + e.z*h.z + e.w*h.w;
        q22 += f.x*f.x + f.y*f.y + f.z*f.z + f.w*f.w;
        q23 += f.x*h.x + f.y*h.y + f.z*h.z + f.w*h.w;
        q33 += h.x*h.x + h.y*h.y + h.z*h.z + h.w*h.w;
    }

    float vals[14] = {s0, s1, s2, s3, q00, q01, q02, q03, q11, q12, q13, q22, q23, q33};

    const int lane = tid & 31;
    const int warp = tid >> 5;
    #pragma unroll
    for (int k = 0; k < 14; k++) {
        #pragma unroll
        for (int o = 16; o > 0; o >>= 1)
            vals[k] += __shfl_down_sync(0xffffffffu, vals[k], o);
    }

    __shared__ float sm[8][14];
    if (lane == 0) {
        #pragma unroll
        for (int k = 0; k < 14; k++) sm[warp][k] = vals[k];
    }
    __syncthreads();
    if (tid < 14) {
        float t = 0.f;
        #pragma unroll
        for (int w = 0; w < 8; w++) t += sm[w][tid];
        g_part[((size_t)g * NB + b) * 14 + tid] = t;
    }

    // Last-block-done bookkeeping.
    __shared__ unsigned int is_last;
    __syncthreads();
    if (tid == 0) {
        __threadfence();                       // publish g_part writes
        unsigned int old = atomicAdd(&g_cnt[g], 1u);
        is_last = (old == NB - 1u) ? 1u : 0u;
        if (is_last) atomicExch(&g_cnt[g], 0u);  // reset for graph replay
    }
    __syncthreads();

    // PDL: this block's streaming contribution is done -> allow the apply
    // grid to begin launching (it will prefetch x, then wait for full
    // completion of this grid before consuming W/bias).
    asm volatile("griddepcontrol.launch_dependents;" ::: "memory");

    if (is_last) {
        solve_group(g);
    }
}

// ---------------------------------------------------------------------------
// Pass 2: apply. grid (NB, NG), fully reversed mapping (L2 residue).
// PDL secondary: prefetch own x tile to L2, then wait for stats grid.
// ---------------------------------------------------------------------------
__global__ __launch_bounds__(256) void apply_kernel(const float* __restrict__ x,
                                                    float* __restrict__ out) {
    const int b = NB - 1 - blockIdx.x;   // reverse b (fast dim)
    const int g = NG - 1 - blockIdx.y;   // reverse g (slow dim)
    const int tid = threadIdx.x;

    const size_t base = ((size_t)b * NCH + (size_t)g * 4) * SP;

    // Prefetch this block's 50176-byte tile (392 x 128B lines) into L2.
    // x is a read-only input, independent of the stats kernel's writes.
    {
        const char* pbase = (const char*)(x + base);
        for (int line = tid; line < 392; line += 256) {
            asm volatile("prefetch.global.L2 [%0];" :: "l"(pbase + (size_t)line * 128));
        }
    }

    // Wait for the stats grid to fully complete (makes g_W/g_bias visible).
    asm volatile("griddepcontrol.wait;" ::: "memory");

    __shared__ float Ws[20];
    if (tid < 16) Ws[tid] = g_W[g * 16 + tid];
    if (tid < 4)  Ws[16 + tid] = g_bias[g * 4 + tid];
    __syncthreads();

    const float w00 = Ws[0],  w01 = Ws[1],  w02 = Ws[2],  w03 = Ws[3];
    const float w10 = Ws[4],  w11 = Ws[5],  w12 = Ws[6],  w13 = Ws[7];
    const float w20 = Ws[8],  w21 = Ws[9],  w22 = Ws[10], w23 = Ws[11];
    const float w30 = Ws[12], w31 = Ws[13], w32 = Ws[14], w33 = Ws[15];
    const float b0 = Ws[16], b1 = Ws[17], b2 = Ws[18], b3 = Ws[19];

    const float4* __restrict__ c0 = (const float4*)(x + base);
    const float4* __restrict__ c1 = c0 + SP4;
    const float4* __restrict__ c2 = c0 + 2 * SP4;
    const float4* __restrict__ c3 = c0 + 3 * SP4;
    float4* __restrict__ o0 = (float4*)(out + base);
    float4* __restrict__ o1 = o0 + SP4;
    float4* __restrict__ o2 = o0 + 2 * SP4;
    float4* __restrict__ o3 = o0 + 3 * SP4;

    for (int i = tid; i < SP4; i += 256) {
        float4 a = __ldcs(c0 + i);
        float4 e = __ldcs(c1 + i);
        float4 f = __ldcs(c2 + i);
        float4 h = __ldcs(c3 + i);

        float4 r0, r1, r2, r3;
        r0.x = fmaf(w00, a.x, fmaf(w01, e.x, fmaf(w02, f.x, fmaf(w03, h.x, -b0))));
        r0.y = fmaf(w00, a.y, fmaf(w01, e.y, fmaf(w02, f.y, fmaf(w03, h.y, -b0))));
        r0.z = fmaf(w00, a.z, fmaf(w01, e.z, fmaf(w02, f.z, fmaf(w03, h.z, -b0))));
        r0.w = fmaf(w00, a.w, fmaf(w01, e.w, fmaf(w02, f.w, fmaf(w03, h.w, -b0))));
        r1.x = fmaf(w10, a.x, fmaf(w11, e.x, fmaf(w12, f.x, fmaf(w13, h.x, -b1))));
        r1.y = fmaf(w10, a.y, fmaf(w11, e.y, fmaf(w12, f.y, fmaf(w13, h.y, -b1))));
        r1.z = fmaf(w10, a.z, fmaf(w11, e.z, fmaf(w12, f.z, fmaf(w13, h.z, -b1))));
        r1.w = fmaf(w10, a.w, fmaf(w11, e.w, fmaf(w12, f.w, fmaf(w13, h.w, -b1))));
        r2.x = fmaf(w20, a.x, fmaf(w21, e.x, fmaf(w22, f.x, fmaf(w23, h.x, -b2))));
        r2.y = fmaf(w20, a.y, fmaf(w21, e.y, fmaf(w22, f.y, fmaf(w23, h.y, -b2))));
        r2.z = fmaf(w20, a.z, fmaf(w21, e.z, fmaf(w22, f.z, fmaf(w23, h.z, -b2))));
        r2.w = fmaf(w20, a.w, fmaf(w21, e.w, fmaf(w22, f.w, fmaf(w23, h.w, -b2))));
        r3.x = fmaf(w30, a.x, fmaf(w31, e.x, fmaf(w32, f.x, fmaf(w33, h.x, -b3))));
        r3.y = fmaf(w30, a.y, fmaf(w31, e.y, fmaf(w32, f.y, fmaf(w33, h.y, -b3))));
        r3.z = fmaf(w30, a.z, fmaf(w31, e.z, fmaf(w32, f.z, fmaf(w33, h.z, -b3))));
        r3.w = fmaf(w30, a.w, fmaf(w31, e.w, fmaf(w32, f.w, fmaf(w33, h.w, -b3))));

        __stcs(o0 + i, r0);
        __stcs(o1 + i, r1);
        __stcs(o2 + i, r2);
        __stcs(o3 + i, r3);
    }
}

// ---------------------------------------------------------------------------
extern "C" void kernel_launch(void* const* d_in, const int* in_sizes, int n_in,
                              void* d_out, int out_size) {
    const float* x = (const float*)d_in[0];
    float* out = (float*)d_out;

    stats_kernel<<<dim3(NB, NG), 256>>>(x);

    // Apply launched as a PDL secondary: it may begin (and prefetch x) while
    // the stats grid's solve tail is still executing.
    cudaLaunchConfig_t cfg = {};
    cfg.gridDim = dim3(NB, NG);
    cfg.blockDim = dim3(256);
    cfg.dynamicSmemBytes = 0;
    cfg.stream = 0;
    cudaLaunchAttribute attrs[1];
    attrs[0].id = cudaLaunchAttributeProgrammaticStreamSerialization;
    attrs[0].val.programmaticStreamSerializationAllowed = 1;
    cfg.attrs = attrs;
    cfg.numAttrs = 1;
    cudaLaunchKernelEx(&cfg, apply_kernel, x, out);
}

// round 15
// speedup vs baseline: 1.0389x; 1.0389x over previous
#include <cuda_runtime.h>

// Group ZCA whitening: x (64, 256, 56, 56) fp32, 64 groups of 4 channels.
// R15: R13 base + (1) warp-parallel Newton-Schulz inverse-sqrt replaces the
// serial Jacobi in the inline solve (last-group tail ~6us -> ~1us); W =
// (C_shrunk + eps*I)^{-1/2} is exactly the reference's U diag(1/sqrt(s+eps)) U^T.
// (2) PDL kept from R14 but WITHOUT the prefetch loop (the prefetch cost
// cancelled the overlap gain; early-launch + wait alone is free).

#define NB   64      // batches
#define NG   64      // groups
#define NCH  256     // channels
#define SP   3136    // 56*56
#define SP4  784     // SP / 4
#define EPSF 1e-3f

__device__ float g_part[NG * NB * 14];   // [group][batch][4 sums + 10 moments]
__device__ float g_W[NG * 16];
__device__ float g_bias[NG * 4];
__device__ unsigned int g_cnt[NG];       // per-group arrival counters (self-resetting)

// ---------------------------------------------------------------------------
// Warp-parallel Newton-Schulz solve for group g. 16 threads each own one
// element (i,j) of the 4x4 matrices; matmuls via shuffles.
// ---------------------------------------------------------------------------
__device__ void solve_group(int g) {
    const int t = threadIdx.x;

    // Reduce the 64 per-batch partials (256 threads; t<64 hold data).
    float vals[14];
    if (t < NB) {
        #pragma unroll
        for (int k = 0; k < 14; k++)
            vals[k] = g_part[((size_t)g * NB + t) * 14 + k];
    } else {
        #pragma unroll
        for (int k = 0; k < 14; k++) vals[k] = 0.f;
    }
    const int lane = t & 31;
    const int warp = t >> 5;
    #pragma unroll
    for (int k = 0; k < 14; k++) {
        #pragma unroll
        for (int o = 16; o > 0; o >>= 1)
            vals[k] += __shfl_down_sync(0xffffffffu, vals[k], o);
    }
    __shared__ float sv[2][14];
    if (lane == 0 && warp < 2) {
        #pragma unroll
        for (int k = 0; k < 14; k++) sv[warp][k] = vals[k];
    }
    __syncthreads();

    if (t < 16) {
        const unsigned int MASK = 0xFFFFu;
        const int i = t >> 2;
        const int j = t & 3;

        float S[4], Q[10];
        #pragma unroll
        for (int k = 0; k < 4; k++) S[k] = sv[0][k] + sv[1][k];
        #pragma unroll
        for (int k = 0; k < 10; k++) Q[k] = sv[0][4 + k] + sv[1][4 + k];

        const float n = (float)NB * (float)SP;
        float m[4];
        #pragma unroll
        for (int k = 0; k < 4; k++) m[k] = S[k] / n;

        // B = (1-eps)*cov + eps*I (shrink) + eps*I (the sqrt(s+eps) shift)
        const int qi[4][4] = {{0,1,2,3},{1,4,5,6},{2,5,7,8},{3,6,8,9}};
        float cov = Q[qi[i][j]] - n * m[i] * m[j];
        float B = (1.0f - EPSF) * cov + ((i == j) ? 2.0f * EPSF : 0.0f);

        // trace(B) for normalization (eigs of Y0 land in (0,1])
        float b00 = __shfl_sync(MASK, B, 0);
        float b11 = __shfl_sync(MASK, B, 5);
        float b22 = __shfl_sync(MASK, B, 10);
        float b33 = __shfl_sync(MASK, B, 15);
        float c = b00 + b11 + b22 + b33;

        float y = B / c;                      // Y0 = B / tr(B)
        float z = (i == j) ? 1.0f : 0.0f;     // Z0 = I

        #pragma unroll
        for (int iter = 0; iter < 12; iter++) {
            // T = Z*Y
            float tsum = 0.f;
            #pragma unroll
            for (int k = 0; k < 4; k++)
                tsum = fmaf(__shfl_sync(MASK, z, i * 4 + k),
                            __shfl_sync(MASK, y, k * 4 + j), tsum);
            // M = (3I - T)/2
            float mm = ((i == j) ? 1.5f : 0.0f) - 0.5f * tsum;
            // Y' = Y*M ; Z' = M*Z
            float ynew = 0.f, znew = 0.f;
            #pragma unroll
            for (int k = 0; k < 4; k++) {
                ynew = fmaf(__shfl_sync(MASK, y, i * 4 + k),
                            __shfl_sync(MASK, mm, k * 4 + j), ynew);
                znew = fmaf(__shfl_sync(MASK, mm, i * 4 + k),
                            __shfl_sync(MASK, z, k * 4 + j), znew);
            }
            y = ynew;
            z = znew;
        }

        // W = Z / sqrt(c);  bias_i = sum_j W[i][j]*m[j]
        float W = z * rsqrtf(c);
        g_W[g * 16 + t] = W;

        float bi = W * m[j];
        bi += __shfl_xor_sync(MASK, bi, 1);
        bi += __shfl_xor_sync(MASK, bi, 2);
        if (j == 0) g_bias[g * 4 + i] = bi;
    }
}

// ---------------------------------------------------------------------------
// Pass 1: stats + inline last-block solve. grid (NB, NG), b fastest (groups
// complete early & staggered; solves trickle during streaming).
// ---------------------------------------------------------------------------
__global__ __launch_bounds__(256, 6) void stats_kernel(const float* __restrict__ x) {
    const int b = blockIdx.x;
    const int g = blockIdx.y;
    const int tid = threadIdx.x;
    const size_t base = ((size_t)b * NCH + (size_t)g * 4) * SP;
    const float4* __restrict__ c0 = (const float4*)(x + base);
    const float4* __restrict__ c1 = c0 + SP4;
    const float4* __restrict__ c2 = c0 + 2 * SP4;
    const float4* __restrict__ c3 = c0 + 3 * SP4;

    float s0 = 0.f, s1 = 0.f, s2 = 0.f, s3 = 0.f;
    float q00 = 0.f, q01 = 0.f, q02 = 0.f, q03 = 0.f;
    float q11 = 0.f, q12 = 0.f, q13 = 0.f;
    float q22 = 0.f, q23 = 0.f, q33 = 0.f;

    for (int i = tid; i < SP4; i += 256) {
        float4 a = c0[i];
        float4 e = c1[i];
        float4 f = c2[i];
        float4 h = c3[i];
        s0 += a.x + a.y + a.z + a.w;
        s1 += e.x + e.y + e.z + e.w;
        s2 += f.x + f.y + f.z + f.w;
        s3 += h.x + h.y + h.z + h.w;
        q00 += a.x*a.x + a.y*a.y + a.z*a.z + a.w*a.w;
        q01 += a.x*e.x + a.y*e.y + a.z*e.z + a.w*e.w;
        q02 += a.x*f.x + a.y*f.y + a.z*f.z + a.w*f.w;
        q03 += a.x*h.x + a.y*h.y + a.z*h.z + a.w*h.w;
        q11 += e.x*e.x + e.y*e.y + e.z*e.z + e.w*e.w;
        q12 += e.x*f.x + e.y*f.y + e.z*f.z + e.w*f.w;
        q13 += e.x*h.x + e.y*h.y + e.z*h.z + e.w*h.w;
        q22 += f.x*f.x + f.y*f.y + f.z*f.z + f.w*f.w;
        q23 += f.x*h.x + f.y*h.y + f.z*h.z + f.w*h.w;
        q33 += h.x*h.x + h.y*h.y + h.z*h.z + h.w*h.w;
    }

    float vals[14] = {s0, s1, s2, s3, q00, q01, q02, q03, q11, q12, q13, q22, q23, q33};

    const int lane = tid & 31;
    const int warp = tid >> 5;
    #pragma unroll
    for (int k = 0; k < 14; k++) {
        #pragma unroll
        for (int o = 16; o > 0; o >>= 1)
            vals[k] += __shfl_down_sync(0xffffffffu, vals[k], o);
    }

    __shared__ float sm[8][14];
    if (lane == 0) {
        #pragma unroll
        for (int k = 0; k < 14; k++) sm[warp][k] = vals[k];
    }
    __syncthreads();
    if (tid < 14) {
        float t = 0.f;
        #pragma unroll
        for (int w = 0; w < 8; w++) t += sm[w][tid];
        g_part[((size_t)g * NB + b) * 14 + tid] = t;
    }

    // Last-block-done bookkeeping.
    __shared__ unsigned int is_last;
    __syncthreads();
    if (tid == 0) {
        __threadfence();                       // publish g_part writes
        unsigned int old = atomicAdd(&g_cnt[g], 1u);
        is_last = (old == NB - 1u) ? 1u : 0u;
        if (is_last) atomicExch(&g_cnt[g], 0u);  // reset for graph replay
    }
    __syncthreads();

    // PDL: streaming contribution done -> let the apply grid start launching.
    asm volatile("griddepcontrol.launch_dependents;" ::: "memory");

    if (is_last) {
        solve_group(g);
    }
}

// ---------------------------------------------------------------------------
// Pass 2: apply. grid (NB, NG), fully reversed mapping (L2 residue).
// PDL secondary: wait for stats grid, then stream (no prefetch -- it cost
// more than the overlap it bought, R14).
// ---------------------------------------------------------------------------
__global__ __launch_bounds__(256) void apply_kernel(const float* __restrict__ x,
                                                    float* __restrict__ out) {
    const int b = NB - 1 - blockIdx.x;   // reverse b (fast dim)
    const int g = NG - 1 - blockIdx.y;   // reverse g (slow dim)
    const int tid = threadIdx.x;

    // Wait for the stats grid to fully complete (makes g_W/g_bias visible).
    asm volatile("griddepcontrol.wait;" ::: "memory");

    __shared__ float Ws[20];
    if (tid < 16) Ws[tid] = g_W[g * 16 + tid];
    if (tid < 4)  Ws[16 + tid] = g_bias[g * 4 + tid];
    __syncthreads();

    const float w00 = Ws[0],  w01 = Ws[1],  w02 = Ws[2],  w03 = Ws[3];
    const float w10 = Ws[4],  w11 = Ws[5],  w12 = Ws[6],  w13 = Ws[7];
    const float w20 = Ws[8],  w21 = Ws[9],  w22 = Ws[10], w23 = Ws[11];
    const float w30 = Ws[12], w31 = Ws[13], w32 = Ws[14], w33 = Ws[15];
    const float b0 = Ws[16], b1 = Ws[17], b2 = Ws[18], b3 = Ws[19];

    const size_t base = ((size_t)b * NCH + (size_t)g * 4) * SP;
    const float4* __restrict__ c0 = (const float4*)(x + base);
    const float4* __restrict__ c1 = c0 + SP4;
    const float4* __restrict__ c2 = c0 + 2 * SP4;
    const float4* __restrict__ c3 = c0 + 3 * SP4;
    float4* __restrict__ o0 = (float4*)(out + base);
    float4* __restrict__ o1 = o0 + SP4;
    float4* __restrict__ o2 = o0 + 2 * SP4;
    float4* __restrict__ o3 = o0 + 3 * SP4;

    for (int i = tid; i < SP4; i += 256) {
        float4 a = __ldcs(c0 + i);
        float4 e = __ldcs(c1 + i);
        float4 f = __ldcs(c2 + i);
        float4 h = __ldcs(c3 + i);

        float4 r0, r1, r2, r3;
        r0.x = fmaf(w00, a.x, fmaf(w01, e.x, fmaf(w02, f.x, fmaf(w03, h.x, -b0))));
        r0.y = fmaf(w00, a.y, fmaf(w01, e.y, fmaf(w02, f.y, fmaf(w03, h.y, -b0))));
        r0.z = fmaf(w00, a.z, fmaf(w01, e.z, fmaf(w02, f.z, fmaf(w03, h.z, -b0))));
        r0.w = fmaf(w00, a.w, fmaf(w01, e.w, fmaf(w02, f.w, fmaf(w03, h.w, -b0))));
        r1.x = fmaf(w10, a.x, fmaf(w11, e.x, fmaf(w12, f.x, fmaf(w13, h.x, -b1))));
        r1.y = fmaf(w10, a.y, fmaf(w11, e.y, fmaf(w12, f.y, fmaf(w13, h.y, -b1))));
        r1.z = fmaf(w10, a.z, fmaf(w11, e.z, fmaf(w12, f.z, fmaf(w13, h.z, -b1))));
        r1.w = fmaf(w10, a.w, fmaf(w11, e.w, fmaf(w12, f.w, fmaf(w13, h.w, -b1))));
        r2.x = fmaf(w20, a.x, fmaf(w21, e.x, fmaf(w22, f.x, fmaf(w23, h.x, -b2))));
        r2.y = fmaf(w20, a.y, fmaf(w21, e.y, fmaf(w22, f.y, fmaf(w23, h.y, -b2))));
        r2.z = fmaf(w20, a.z, fmaf(w21, e.z, fmaf(w22, f.z, fmaf(w23, h.z, -b2))));
        r2.w = fmaf(w20, a.w, fmaf(w21, e.w, fmaf(w22, f.w, fmaf(w23, h.w, -b2))));
        r3.x = fmaf(w30, a.x, fmaf(w31, e.x, fmaf(w32, f.x, fmaf(w33, h.x, -b3))));
        r3.y = fmaf(w30, a.y, fmaf(w31, e.y, fmaf(w32, f.y, fmaf(w33, h.y, -b3))));
        r3.z = fmaf(w30, a.z, fmaf(w31, e.z, fmaf(w32, f.z, fmaf(w33, h.z, -b3))));
        r3.w = fmaf(w30, a.w, fmaf(w31, e.w, fmaf(w32, f.w, fmaf(w33, h.w, -b3))));

        __stcs(o0 + i, r0);
        __stcs(o1 + i, r1);
        __stcs(o2 + i, r2);
        __stcs(o3 + i, r3);
    }
}

// ---------------------------------------------------------------------------
extern "C" void kernel_launch(void* const* d_in, const int* in_sizes, int n_in,
                              void* d_out, int out_size) {
    const float* x = (const float*)d_in[0];
    float* out = (float*)d_out;

    stats_kernel<<<dim3(NB, NG), 256>>>(x);

    cudaLaunchConfig_t cfg = {};
    cfg.gridDim = dim3(NB, NG);
    cfg.blockDim = dim3(256);
    cfg.dynamicSmemBytes = 0;
    cfg.stream = 0;
    cudaLaunchAttribute attrs[1];
    attrs[0].id = cudaLaunchAttributeProgrammaticStreamSerialization;
    attrs[0].val.programmaticStreamSerializationAllowed = 1;
    cfg.attrs = attrs;
    cfg.numAttrs = 1;
    cudaLaunchKernelEx(&cfg, apply_kernel, x, out);
}